// round 2
// baseline (speedup 1.0000x reference)
#include <cuda_runtime.h>

#define NR 2097152              // rows
#define K  7                    // clusters
#define TPB 256
#define NBLOCKS 2048
#define NTHREADS (NBLOCKS * TPB)    // 524288
#define REPS (NR / NTHREADS)        // 4 rows per thread, exact

// E stored row-major padded to 8 floats/row (col 7 = 0): two float4 per row.
static __device__ float4   g_E4[(size_t)NR * 2];
static __device__ double   g_S[K];        // reduction accumulators T_j
static __device__ double   g_b[K];        // current b (double, for exact err/pow)
static __device__ float    g_fb[8];       // float b for bulk kernels (fb[7]=0)
static __device__ float    g_fbprev[8];   // previous b (for final plan)
static __device__ int      g_conv;        // convergence flag
static __device__ unsigned g_done;        // last-block counter

__constant__ double c_Pb[K] = {0.17, 0.14, 0.15, 0.12, 0.05, 0.13, 0.24};

// ---------------------------------------------------------------------------
// Block reduction of K float partials -> double -> atomicAdd into g_S
// ---------------------------------------------------------------------------
__device__ __forceinline__ void block_reduce_atomic(float acc[K]) {
#pragma unroll
    for (int j = 0; j < K; j++) {
#pragma unroll
        for (int off = 16; off > 0; off >>= 1)
            acc[j] += __shfl_down_sync(0xffffffffu, acc[j], off);
    }
    __shared__ double sm[TPB / 32][K];
    int w = threadIdx.x >> 5;
    if ((threadIdx.x & 31) == 0) {
#pragma unroll
        for (int j = 0; j < K; j++) sm[w][j] = (double)acc[j];
    }
    __syncthreads();
    if (threadIdx.x < K) {
        double s = 0.0;
#pragma unroll
        for (int ww = 0; ww < TPB / 32; ww++) s += sm[ww][threadIdx.x];
        atomicAdd(&g_S[threadIdx.x], s);
    }
    __syncthreads();   // all block atomics issued before counter bump
}

// ---------------------------------------------------------------------------
// Last-block epilogue: b update, err, convergence — fused, no extra launch.
// ---------------------------------------------------------------------------
__device__ __forceinline__ void finalize_update(int first) {
    __shared__ int is_last;
    if (threadIdx.x == 0) {
        __threadfence();
        unsigned t = atomicAdd(&g_done, 1u);
        is_last = (t == (unsigned)(gridDim.x - 1));
    }
    __syncthreads();
    if (is_last && threadIdx.x == 0) {
        __threadfence();      // acquire: see all blocks' g_S atomics
        g_done = 0;
        const double FI = 1.0 / 1.1;   // gamma/(gamma+eps)
        double nb[K];
        double err2 = 0.0;
#pragma unroll
        for (int j = 0; j < K; j++) {
            double v = (double)NR * c_Pb[j] / g_S[j];   // b_j = Pb_j / (Q^T a)_j
            nb[j] = pow(v, FI);                          // SEMI_USE exponent
            double d = nb[j] - g_b[j];
            err2 += d * d;
        }
        if (first) err2 += 0.015625;   // b[7]: 1/8 -> 0 on iteration 1
#pragma unroll
        for (int j = 0; j < K; j++) {
            g_fbprev[j] = (float)g_b[j];
            g_b[j] = nb[j];
            g_fb[j] = (float)nb[j];
            g_S[j] = 0.0;              // reset for next pass
        }
        if (sqrt(err2) <= 1e-6) g_conv = 1;
    }
}

// ---------------------------------------------------------------------------
__global__ void k_init() {
    int j = threadIdx.x;
    if (j < K) {
        g_S[j] = 0.0;
        g_b[j] = 0.125;
        g_fb[j] = 0.125f;
        g_fbprev[j] = 0.125f;
    }
    if (j == 7) { g_fb[7] = 0.f; g_fbprev[7] = 0.f; }
    if (j == 0) { g_conv = 0; g_done = 0; }
}

// ---------------------------------------------------------------------------
// Precompute E (row-major, padded to 8) + fused Sinkhorn iteration 1.
// r_i = softmax-denominator^-10 lives in a register only.
// ---------------------------------------------------------------------------
__global__ void __launch_bounds__(TPB) k_pre(const float* __restrict__ P) {
    int tid = blockIdx.x * TPB + threadIdx.x;
    float acc[K];
#pragma unroll
    for (int j = 0; j < K; j++) acc[j] = 0.f;

    for (int rep = 0; rep < REPS; rep++) {
        int i = tid + rep * NTHREADS;
        const float* row = P + (size_t)i * K;
        float p[K];
#pragma unroll
        for (int j = 0; j < K; j++) p[j] = row[j];
        float m = p[0];
#pragma unroll
        for (int j = 1; j < K; j++) m = fmaxf(m, p[j]);
        float s1 = 0.f, sE = 0.f;
        float E[K];
#pragma unroll
        for (int j = 0; j < K; j++) {
            float t = expf(p[j] - m);          // softmax numerator (unnormed)
            s1 += t;
            float t2 = t * t, t4 = t2 * t2, t8 = t4 * t4;
            E[j] = t8 * t2;                    // exp(10*(p-m)) = t^10
            sE += E[j];
        }
        g_E4[(size_t)i * 2 + 0] = make_float4(E[0], E[1], E[2], E[3]);
        g_E4[(size_t)i * 2 + 1] = make_float4(E[4], E[5], E[6], 0.f);
        float s2 = s1 * s1, s4 = s2 * s2, s8 = s4 * s4, s10 = s8 * s2;
        float r = 1.f / s10;                   // r_i = s1^-10 in (3.5e-9, 1]
        float w = 8.f * r / (r * sE + 1.f);
#pragma unroll
        for (int j = 0; j < K; j++) acc[j] += w * E[j];
    }
    block_reduce_atomic(acc);
    finalize_update(1);
}

// ---------------------------------------------------------------------------
// Sinkhorn iteration t>=2: T_j = sum_i E_ij / (E_i . b)
// Two LDG.128 per row, fully unrolled over REPS=4 -> 8 loads in flight/thread.
// ---------------------------------------------------------------------------
__global__ void __launch_bounds__(TPB) k_iter() {
    if (g_conv) return;
    float b[8];
#pragma unroll
    for (int j = 0; j < 8; j++) b[j] = g_fb[j];
    int tid = blockIdx.x * TPB + threadIdx.x;
    float acc[K];
#pragma unroll
    for (int j = 0; j < K; j++) acc[j] = 0.f;

    float4 v0[REPS], v1[REPS];
#pragma unroll
    for (int rep = 0; rep < REPS; rep++) {
        size_t i = (size_t)(tid + rep * NTHREADS) * 2;
        v0[rep] = g_E4[i];
        v1[rep] = g_E4[i + 1];
    }
#pragma unroll
    for (int rep = 0; rep < REPS; rep++) {
        float dot;
        dot = v0[rep].x * b[0];
        dot = fmaf(v0[rep].y, b[1], dot);
        dot = fmaf(v0[rep].z, b[2], dot);
        dot = fmaf(v0[rep].w, b[3], dot);
        dot = fmaf(v1[rep].x, b[4], dot);
        dot = fmaf(v1[rep].y, b[5], dot);
        dot = fmaf(v1[rep].z, b[6], dot);
        float inv = 1.f / dot;                 // row max of E is 1 -> dot > 0
        acc[0] = fmaf(v0[rep].x, inv, acc[0]);
        acc[1] = fmaf(v0[rep].y, inv, acc[1]);
        acc[2] = fmaf(v0[rep].z, inv, acc[2]);
        acc[3] = fmaf(v0[rep].w, inv, acc[3]);
        acc[4] = fmaf(v1[rep].x, inv, acc[4]);
        acc[5] = fmaf(v1[rep].y, inv, acc[5]);
        acc[6] = fmaf(v1[rep].z, inv, acc[6]);
    }
    block_reduce_atomic(acc);
    finalize_update(0);
}

// ---------------------------------------------------------------------------
// plan_ij = E_ij * b_j / (E_i . b_prev). Output row-major [n,7] fp32.
// ---------------------------------------------------------------------------
__global__ void __launch_bounds__(TPB) k_final(float* __restrict__ out) {
    float bn[8], bp[8];
#pragma unroll
    for (int j = 0; j < 8; j++) { bn[j] = g_fb[j]; bp[j] = g_fbprev[j]; }
    int tid = blockIdx.x * TPB + threadIdx.x;

#pragma unroll
    for (int rep = 0; rep < REPS; rep++) {
        int i = tid + rep * NTHREADS;
        float4 v0 = g_E4[(size_t)i * 2];
        float4 v1 = g_E4[(size_t)i * 2 + 1];
        float dot;
        dot = v0.x * bp[0];
        dot = fmaf(v0.y, bp[1], dot);
        dot = fmaf(v0.z, bp[2], dot);
        dot = fmaf(v0.w, bp[3], dot);
        dot = fmaf(v1.x, bp[4], dot);
        dot = fmaf(v1.y, bp[5], dot);
        dot = fmaf(v1.z, bp[6], dot);
        float inv = 1.f / dot;
        float* o = out + (size_t)i * K;
        o[0] = v0.x * bn[0] * inv;
        o[1] = v0.y * bn[1] * inv;
        o[2] = v0.z * bn[2] * inv;
        o[3] = v0.w * bn[3] * inv;
        o[4] = v1.x * bn[4] * inv;
        o[5] = v1.y * bn[5] * inv;
        o[6] = v1.z * bn[6] * inv;
    }
}

// ---------------------------------------------------------------------------
extern "C" void kernel_launch(void* const* d_in, const int* in_sizes, int n_in,
                              void* d_out, int out_size) {
    const float* P = (const float*)d_in[0];
    float* out = (float*)d_out;
    (void)in_sizes; (void)n_in; (void)out_size;

    k_init<<<1, 32>>>();
    k_pre<<<NBLOCKS, TPB>>>(P);          // builds E + Sinkhorn iter 1
    for (int t = 0; t < 49; t++)         // iters 2..50; no-op after convergence
        k_iter<<<NBLOCKS, TPB>>>();
    k_final<<<NBLOCKS, TPB>>>(out);
}

// round 3
// speedup vs baseline: 1.0182x; 1.0182x over previous
#include <cuda_runtime.h>
#include <cuda_fp16.h>

#define NR 2097152              // rows
#define K  7                    // clusters
#define TPB 256
#define NBLOCKS 2048
#define NTHREADS (NBLOCKS * TPB)    // 524288
#define REPS (NR / NTHREADS)        // 4 rows per thread (pre/final)

// Iteration kernel tiling
#define IT_BLOCKS 2048
#define IT_ROWS_PER_BLOCK (NR / IT_BLOCKS)   // 1024
#define IT_CHUNK_ROWS 512
#define IT_CHUNK_BYTES (IT_CHUNK_ROWS * 16)  // 8192
#define IT_NCHUNK (IT_ROWS_PER_BLOCK / IT_CHUNK_ROWS)  // 2

// E stored as fp16, padded to 8 halves/row (pad = 0): 16 B/row, 32 MB total.
static __device__ __align__(128) __half g_E16[(size_t)NR * 8];
static __device__ double   g_S[K];        // reduction accumulators T_j
static __device__ double   g_b[K];        // current b (double, for exact err/pow)
static __device__ float    g_fb[8];       // float b for bulk kernels (fb[7]=0)
static __device__ float    g_fbprev[8];   // previous b (for final plan)
static __device__ int      g_conv;        // convergence flag
static __device__ unsigned g_done;        // last-block counter

__constant__ double c_Pb[K] = {0.17, 0.14, 0.15, 0.12, 0.05, 0.13, 0.24};

// ---------------------------------------------------------------------------
// mbarrier / bulk-copy PTX helpers (cta scope)
// ---------------------------------------------------------------------------
__device__ __forceinline__ unsigned smem_u32(const void* p) {
    return (unsigned)__cvta_generic_to_shared(p);
}
#define MBAR_INIT(a, c) \
    asm volatile("mbarrier.init.shared.b64 [%0], %1;" :: "r"(a), "r"(c) : "memory")
#define MBAR_EXPECT_TX(a, bytes) \
    asm volatile("mbarrier.arrive.expect_tx.shared.b64 _, [%0], %1;" \
                 :: "r"(a), "r"(bytes) : "memory")
#define BULK_G2S(dst, src, bytes, mbar) \
    asm volatile("cp.async.bulk.shared::cta.global.mbarrier::complete_tx::bytes " \
                 "[%0], [%1], %2, [%3];" \
                 :: "r"(dst), "l"(src), "r"(bytes), "r"(mbar) : "memory")

__device__ __forceinline__ void mbar_wait_parity(unsigned mbar, unsigned parity) {
    unsigned done;
    asm volatile(
        "{\n\t.reg .pred p;\n\t"
        "mbarrier.try_wait.parity.acquire.cta.shared::cta.b64 p, [%1], %2;\n\t"
        "selp.b32 %0, 1, 0, p;\n\t}"
        : "=r"(done) : "r"(mbar), "r"(parity) : "memory");
    if (!done) {
        asm volatile(
            "{\n\t.reg .pred P1;\n\t"
            "WAIT_LOOP_%=:\n\t"
            "mbarrier.try_wait.parity.acquire.cta.shared::cta.b64 P1, [%0], %1, 0x989680;\n\t"
            "@P1 bra.uni WAIT_DONE_%=;\n\t"
            "bra.uni WAIT_LOOP_%=;\n\t"
            "WAIT_DONE_%=:\n\t}"
            :: "r"(mbar), "r"(parity) : "memory");
    }
}

// ---------------------------------------------------------------------------
// Block reduction of K float partials -> double -> atomicAdd into g_S
// ---------------------------------------------------------------------------
__device__ __forceinline__ void block_reduce_atomic(float acc[K], int tpb) {
#pragma unroll
    for (int j = 0; j < K; j++) {
#pragma unroll
        for (int off = 16; off > 0; off >>= 1)
            acc[j] += __shfl_down_sync(0xffffffffu, acc[j], off);
    }
    __shared__ double sm[TPB / 32][K];
    int w = threadIdx.x >> 5;
    if ((threadIdx.x & 31) == 0) {
#pragma unroll
        for (int j = 0; j < K; j++) sm[w][j] = (double)acc[j];
    }
    __syncthreads();
    if (threadIdx.x < K) {
        double s = 0.0;
#pragma unroll
        for (int ww = 0; ww < tpb / 32; ww++) s += sm[ww][threadIdx.x];
        atomicAdd(&g_S[threadIdx.x], s);
    }
    __syncthreads();   // all block atomics issued before counter bump
}

// ---------------------------------------------------------------------------
// Last-block epilogue: b update, err, convergence — fused, no extra launch.
// ---------------------------------------------------------------------------
__device__ __forceinline__ void finalize_update(int first, unsigned nblocks) {
    __shared__ int is_last;
    if (threadIdx.x == 0) {
        __threadfence();
        unsigned t = atomicAdd(&g_done, 1u);
        is_last = (t == nblocks - 1u);
    }
    __syncthreads();
    if (is_last && threadIdx.x == 0) {
        __threadfence();      // acquire: see all blocks' g_S atomics
        g_done = 0;
        const double FI = 1.0 / 1.1;   // gamma/(gamma+eps)
        double nb[K];
        double err2 = 0.0;
#pragma unroll
        for (int j = 0; j < K; j++) {
            double v = (double)NR * c_Pb[j] / g_S[j];   // b_j = Pb_j / (Q^T a)_j
            nb[j] = pow(v, FI);                          // SEMI_USE exponent
            double d = nb[j] - g_b[j];
            err2 += d * d;
        }
        if (first) err2 += 0.015625;   // b[7]: 1/8 -> 0 on iteration 1
#pragma unroll
        for (int j = 0; j < K; j++) {
            g_fbprev[j] = (float)g_b[j];
            g_b[j] = nb[j];
            g_fb[j] = (float)nb[j];
            g_S[j] = 0.0;              // reset for next pass
        }
        if (sqrt(err2) <= 1e-6) g_conv = 1;
    }
}

// ---------------------------------------------------------------------------
__global__ void k_init() {
    int j = threadIdx.x;
    if (j < K) {
        g_S[j] = 0.0;
        g_b[j] = 0.125;
        g_fb[j] = 0.125f;
        g_fbprev[j] = 0.125f;
    }
    if (j == 7) { g_fb[7] = 0.f; g_fbprev[7] = 0.f; }
    if (j == 0) { g_conv = 0; g_done = 0; }
}

// ---------------------------------------------------------------------------
// Row kernel helper: E (fp32) from a P row. r_i (softmax denom^-10) is
// register-only.
// ---------------------------------------------------------------------------
__device__ __forceinline__ void compute_E_row(const float* __restrict__ row,
                                              float E[K], float* r_out) {
    float p[K];
#pragma unroll
    for (int j = 0; j < K; j++) p[j] = row[j];
    float m = p[0];
#pragma unroll
    for (int j = 1; j < K; j++) m = fmaxf(m, p[j]);
    float s1 = 0.f;
#pragma unroll
    for (int j = 0; j < K; j++) {
        float t = expf(p[j] - m);
        s1 += t;
        float t2 = t * t, t4 = t2 * t2, t8 = t4 * t4;
        E[j] = t8 * t2;                // exp(10*(p-m)) = t^10
    }
    float s2 = s1 * s1, s4 = s2 * s2, s8 = s4 * s4;
    *r_out = 1.f / (s8 * s2);          // s1^-10
}

// ---------------------------------------------------------------------------
// Precompute E16 (fp16, padded to 8) + fused Sinkhorn iteration 1.
// ---------------------------------------------------------------------------
__global__ void __launch_bounds__(TPB) k_pre(const float* __restrict__ P) {
    int tid = blockIdx.x * TPB + threadIdx.x;
    float acc[K];
#pragma unroll
    for (int j = 0; j < K; j++) acc[j] = 0.f;

    for (int rep = 0; rep < REPS; rep++) {
        int i = tid + rep * NTHREADS;
        float E[K], r;
        compute_E_row(P + (size_t)i * K, E, &r);

        __half2 h01 = __floats2half2_rn(E[0], E[1]);
        __half2 h23 = __floats2half2_rn(E[2], E[3]);
        __half2 h45 = __floats2half2_rn(E[4], E[5]);
        __half2 h67 = __floats2half2_rn(E[6], 0.f);
        uint4 u;
        u.x = *reinterpret_cast<unsigned*>(&h01);
        u.y = *reinterpret_cast<unsigned*>(&h23);
        u.z = *reinterpret_cast<unsigned*>(&h45);
        u.w = *reinterpret_cast<unsigned*>(&h67);
        reinterpret_cast<uint4*>(g_E16)[i] = u;

        float sE = E[0] + E[1] + E[2] + E[3] + E[4] + E[5] + E[6];
        float w = 8.f * r / (r * sE + 1.f);    // iter-1 weight (b uniform 1/8)
#pragma unroll
        for (int j = 0; j < K; j++) acc[j] += w * E[j];
    }
    block_reduce_atomic(acc, TPB);
    finalize_update(1, NBLOCKS);
}

// ---------------------------------------------------------------------------
// Sinkhorn iteration t>=2: T_j = sum_i E_ij / (E_i . b)
// cp.async.bulk double-buffered SMEM pipeline — bypasses the per-SM LDG
// outstanding-miss cap that limited rounds 1-2 to ~1.4 TB/s.
// ---------------------------------------------------------------------------
__global__ void __launch_bounds__(TPB) k_iter() {
    if (g_conv) return;

    __shared__ __align__(128) uint4 buf[2][IT_CHUNK_ROWS];
    __shared__ __align__(8) unsigned long long mbar[2];

    int tid = threadIdx.x;
    unsigned mb[2] = { smem_u32(&mbar[0]), smem_u32(&mbar[1]) };
    if (tid == 0) { MBAR_INIT(mb[0], 1); MBAR_INIT(mb[1], 1); }
    asm volatile("fence.proxy.async.shared::cta;" ::: "memory");
    __syncthreads();

    const __half* src = g_E16 + (size_t)blockIdx.x * IT_ROWS_PER_BLOCK * 8;
    if (tid == 0) {
#pragma unroll
        for (int c = 0; c < IT_NCHUNK; c++) {
            MBAR_EXPECT_TX(mb[c], IT_CHUNK_BYTES);
            BULK_G2S(smem_u32(&buf[c][0]),
                     src + (size_t)c * IT_CHUNK_ROWS * 8,
                     IT_CHUNK_BYTES, mb[c]);
        }
    }

    float b[8];
#pragma unroll
    for (int j = 0; j < 8; j++) b[j] = g_fb[j];
    float acc[K];
#pragma unroll
    for (int j = 0; j < K; j++) acc[j] = 0.f;

#pragma unroll
    for (int c = 0; c < IT_NCHUNK; c++) {
        mbar_wait_parity(mb[c], 0u);
#pragma unroll
        for (int r = 0; r < IT_CHUNK_ROWS / TPB; r++) {
            uint4 v = buf[c][tid + r * TPB];
            const __half2* h2 = reinterpret_cast<const __half2*>(&v);
            float2 f0 = __half22float2(h2[0]);
            float2 f1 = __half22float2(h2[1]);
            float2 f2 = __half22float2(h2[2]);
            float2 f3 = __half22float2(h2[3]);
            float dot = f0.x * b[0];
            dot = fmaf(f0.y, b[1], dot);
            dot = fmaf(f1.x, b[2], dot);
            dot = fmaf(f1.y, b[3], dot);
            dot = fmaf(f2.x, b[4], dot);
            dot = fmaf(f2.y, b[5], dot);
            dot = fmaf(f3.x, b[6], dot);
            float inv = 1.f / dot;             // row max of E is 1 -> dot > 0
            acc[0] = fmaf(f0.x, inv, acc[0]);
            acc[1] = fmaf(f0.y, inv, acc[1]);
            acc[2] = fmaf(f1.x, inv, acc[2]);
            acc[3] = fmaf(f1.y, inv, acc[3]);
            acc[4] = fmaf(f2.x, inv, acc[4]);
            acc[5] = fmaf(f2.y, inv, acc[5]);
            acc[6] = fmaf(f3.x, inv, acc[6]);
        }
    }
    block_reduce_atomic(acc, TPB);
    finalize_update(0, IT_BLOCKS);
}

// ---------------------------------------------------------------------------
// Final plan: recompute E in fp32 from P (full precision — fp16 storage never
// touches the output path).  plan_ij = E_ij * bn_j / (E_i . bp).
// ---------------------------------------------------------------------------
__global__ void __launch_bounds__(TPB) k_final(const float* __restrict__ P,
                                               float* __restrict__ out) {
    float bn[K], bp[K];
#pragma unroll
    for (int j = 0; j < K; j++) { bn[j] = g_fb[j]; bp[j] = g_fbprev[j]; }
    int tid = blockIdx.x * TPB + threadIdx.x;

    for (int rep = 0; rep < REPS; rep++) {
        int i = tid + rep * NTHREADS;
        float E[K], r;
        compute_E_row(P + (size_t)i * K, E, &r);
        float dot = E[0] * bp[0];
#pragma unroll
        for (int j = 1; j < K; j++) dot = fmaf(E[j], bp[j], dot);
        float inv = 1.f / dot;
        float* o = out + (size_t)i * K;
#pragma unroll
        for (int j = 0; j < K; j++) o[j] = E[j] * bn[j] * inv;
    }
}

// ---------------------------------------------------------------------------
extern "C" void kernel_launch(void* const* d_in, const int* in_sizes, int n_in,
                              void* d_out, int out_size) {
    const float* P = (const float*)d_in[0];
    float* out = (float*)d_out;
    (void)in_sizes; (void)n_in; (void)out_size;

    k_init<<<1, 32>>>();
    k_pre<<<NBLOCKS, TPB>>>(P);          // builds E16 + Sinkhorn iter 1
    for (int t = 0; t < 49; t++)         // iters 2..50; no-op after convergence
        k_iter<<<IT_BLOCKS, TPB>>>();
    k_final<<<NBLOCKS, TPB>>>(P, out);
}

// round 4
// speedup vs baseline: 3.5098x; 3.4471x over previous
#include <cuda_runtime.h>
#include <cuda_fp16.h>

#define NR   2097152
#define K    7
#define GRID 148                 // <= SM count (148 B300 / 152 GB300): all resident
#define TPB  512
#define RPB  14172               // rows per block (multiple of 4); last block: 13868
#define NIT  50

static __device__ double   g_S[NIT + 1][8];   // per-iteration reduction slots
static __device__ unsigned g_bar;             // grid barrier counter (monotonic)

__constant__ double c_Pb[K] = {0.17, 0.14, 0.15, 0.12, 0.05, 0.13, 0.24};

struct Scratch {
    double warp[TPB / 32][K];   // block reduction staging
    double b[K];                // current b (double, exact chain)
    double bp[K];               // previous b
    double d2[K];               // per-component squared diffs
};

#define DYN_SMEM ((size_t)RPB * 16 + sizeof(Scratch))

// ---------------------------------------------------------------------------
// exp2 for x <= 0, FMA-pipe polynomial (no MUFU). |f|<=0.5 Taylor deg-6,
// max rel err ~1.2e-7. Underflow (2^n, n < -126) flushed to 0.
// ---------------------------------------------------------------------------
__device__ __forceinline__ float exp2n(float x) {
    float n = rintf(x);
    float f = x - n;
    float p = fmaf(f, 1.54035304e-4f, 1.33335581e-3f);
    p = fmaf(p, f, 9.61812910e-3f);
    p = fmaf(p, f, 5.55041087e-2f);
    p = fmaf(p, f, 2.40226507e-1f);
    p = fmaf(p, f, 6.93147181e-1f);
    p = fmaf(p, f, 1.0f);
    int ni = __float2int_rn(n);
    if (ni < -126) return 0.0f;
    return p * __int_as_float((ni + 127) << 23);
}

// ---------------------------------------------------------------------------
// Reciprocal without MUFU: magic-constant seed + 3 Newton steps (err -> <1e-7)
// ---------------------------------------------------------------------------
__device__ __forceinline__ float frcp(float x) {
    float y = __int_as_float(0x7EF311C3 - __float_as_int(x));
    y = y * fmaf(-x, y, 2.0f);
    y = y * fmaf(-x, y, 2.0f);
    y = y * fmaf(-x, y, 2.0f);
    return y;
}

// ---------------------------------------------------------------------------
// Grid barrier: all GRID blocks resident (1 CTA/SM by smem), monotonic target.
// ---------------------------------------------------------------------------
__device__ __forceinline__ void grid_bar(unsigned target) {
    __syncthreads();
    if (threadIdx.x == 0) {
        atomicAdd(&g_bar, 1u);
        while (atomicAdd(&g_bar, 0u) < target) { }
    }
    __syncthreads();
}

// ---------------------------------------------------------------------------
// Block-reduce K fp32 partials -> double -> atomicAdd into g_S[it]
// ---------------------------------------------------------------------------
__device__ __forceinline__ void publish(Scratch* sc, float acc[K], int it) {
    int tid = threadIdx.x;
#pragma unroll
    for (int j = 0; j < K; j++) {
#pragma unroll
        for (int off = 16; off > 0; off >>= 1)
            acc[j] += __shfl_down_sync(0xffffffffu, acc[j], off);
    }
    int w = tid >> 5;
    if ((tid & 31) == 0) {
#pragma unroll
        for (int j = 0; j < K; j++) sc->warp[w][j] = (double)acc[j];
    }
    __syncthreads();
    if (tid < K) {
        double s = 0.0;
#pragma unroll
        for (int ww = 0; ww < TPB / 32; ww++) s += sc->warp[ww][tid];
        atomicAdd(&g_S[it][tid], s);
        __threadfence();   // release our g_S contribution before barrier arrive
    }
}

// ---------------------------------------------------------------------------
// b update, computed redundantly & identically by every block. Returns err.
// ---------------------------------------------------------------------------
__device__ __forceinline__ double b_update(Scratch* sc, int it, int first) {
    int tid = threadIdx.x;
    __threadfence();           // acquire side for g_S reads
    if (tid < K) {
        double S = g_S[it][tid];                  // fresh slot: never in L1
        double v = (double)NR * c_Pb[tid] / S;    // b_j = Pb_j / (Q^T a)_j
        double nb = pow(v, 1.0 / 1.1);            // SEMI_USE exponent
        double old = sc->b[tid];
        sc->bp[tid] = old;
        sc->b[tid] = nb;
        double d = nb - old;
        sc->d2[tid] = d * d;
    }
    __syncthreads();
    double e2 = sc->d2[0] + sc->d2[1] + sc->d2[2] + sc->d2[3]
              + sc->d2[4] + sc->d2[5] + sc->d2[6];
    if (first) e2 += 0.015625;   // b[7]: 1/8 -> 0 on iteration 1
    return sqrt(e2);
}

// ---------------------------------------------------------------------------
__global__ void k_init() {
    int t = threadIdx.x;
    if (t == 0) g_bar = 0u;
    double* p = &g_S[0][0];
    for (int i = t; i < (NIT + 1) * 8; i += blockDim.x) p[i] = 0.0;
}

// ---------------------------------------------------------------------------
// Persistent fused kernel: pre + all Sinkhorn iterations + final plan.
// E (fp16, 16 B/row) lives in this block's SMEM for the whole run.
// ---------------------------------------------------------------------------
__global__ void __launch_bounds__(TPB, 1)
k_main(const float* __restrict__ P, float* __restrict__ out) {
    extern __shared__ __align__(16) unsigned char dyn[];
    uint4*   Es = reinterpret_cast<uint4*>(dyn);                 // [nrows]
    Scratch* sc = reinterpret_cast<Scratch*>(dyn + (size_t)RPB * 16);

    const int tid   = threadIdx.x;
    const int base  = blockIdx.x * RPB;
    const int nrows = min(RPB, NR - base);
    const int ngrp  = nrows >> 2;          // groups of 4 rows (exact)
    unsigned phase = 0;

    if (tid < K) { sc->b[tid] = 0.125; sc->bp[tid] = 0.125; }
    __syncthreads();

    // ---- Phase A: build E in SMEM + iteration-1 partials --------------------
    // Iter 1 closed form: w_i = 8 r_i / (r_i*sumE_i + 1), r_i = s1^-10 (register-only)
    const float K10 = 14.4269504f;   // 10*log2(e)
    const float K1  = 1.44269504f;   // log2(e)
    float acc[K];
#pragma unroll
    for (int j = 0; j < K; j++) acc[j] = 0.f;

    for (int g = tid; g < ngrp; g += TPB) {
        const uint4* ps = reinterpret_cast<const uint4*>(P + (size_t)(base + (g << 2)) * K);
        uint4 q[7];
#pragma unroll
        for (int i = 0; i < 7; i++) q[i] = ps[i];   // 4 rows = 28 floats, coalesced
        const float* pf = reinterpret_cast<const float*>(q);
#pragma unroll
        for (int r = 0; r < 4; r++) {
            const float* pr = pf + r * 7;
            float m = pr[0];
#pragma unroll
            for (int j = 1; j < K; j++) m = fmaxf(m, pr[j]);
            float E[K];
            float s1 = 0.f, sE = 0.f;
#pragma unroll
            for (int j = 0; j < K; j++) {
                float d = pr[j] - m;
                E[j] = exp2n(K10 * d);     // exp(10*(p-m))
                s1  += exp2n(K1 * d);      // exp(p-m)
                sE  += E[j];
            }
            __half2 h0 = __floats2half2_rn(E[0], E[1]);
            __half2 h1 = __floats2half2_rn(E[2], E[3]);
            __half2 h2 = __floats2half2_rn(E[4], E[5]);
            __half2 h3 = __floats2half2_rn(E[6], 0.f);
            uint4 u;
            u.x = *reinterpret_cast<unsigned*>(&h0);
            u.y = *reinterpret_cast<unsigned*>(&h1);
            u.z = *reinterpret_cast<unsigned*>(&h2);
            u.w = *reinterpret_cast<unsigned*>(&h3);
            Es[(g << 2) + r] = u;

            float s2 = s1 * s1, s4 = s2 * s2, s8 = s4 * s4;
            float r10 = frcp(s8 * s2);                  // s1^-10
            float w = 8.f * r10 * frcp(fmaf(r10, sE, 1.f));
#pragma unroll
            for (int j = 0; j < K; j++) acc[j] = fmaf(w, E[j], acc[j]);
        }
    }
    publish(sc, acc, 1);
    grid_bar(GRID * (++phase));
    int it = 1;
    double err = b_update(sc, 1, 1);

    // ---- Iterations 2..50: SMEM-only passes ---------------------------------
    while (err > 1e-6 && it < NIT) {
        it++;
        float bf[K];
#pragma unroll
        for (int j = 0; j < K; j++) bf[j] = (float)sc->b[j];
        float a2[K];
#pragma unroll
        for (int j = 0; j < K; j++) a2[j] = 0.f;

        for (int idx = tid; idx < nrows; idx += TPB) {
            uint4 v = Es[idx];
            const __half2* h = reinterpret_cast<const __half2*>(&v);
            float2 f0 = __half22float2(h[0]);
            float2 f1 = __half22float2(h[1]);
            float2 f2 = __half22float2(h[2]);
            float2 f3 = __half22float2(h[3]);
            float dot = f0.x * bf[0];
            dot = fmaf(f0.y, bf[1], dot);
            dot = fmaf(f1.x, bf[2], dot);
            dot = fmaf(f1.y, bf[3], dot);
            dot = fmaf(f2.x, bf[4], dot);
            dot = fmaf(f2.y, bf[5], dot);
            dot = fmaf(f3.x, bf[6], dot);
            float inv = frcp(dot);          // FMA-pipe reciprocal (no MUFU floor)
            a2[0] = fmaf(f0.x, inv, a2[0]);
            a2[1] = fmaf(f0.y, inv, a2[1]);
            a2[2] = fmaf(f1.x, inv, a2[2]);
            a2[3] = fmaf(f1.y, inv, a2[3]);
            a2[4] = fmaf(f2.x, inv, a2[4]);
            a2[5] = fmaf(f2.y, inv, a2[5]);
            a2[6] = fmaf(f3.x, inv, a2[6]);
        }
        publish(sc, a2, it);
        grid_bar(GRID * (++phase));
        err = b_update(sc, it, 0);
    }

    // ---- Final: plan_ij = E_ij * bn_j / (E_i . bp), from SMEM ---------------
    float bn[K], bp[K];
#pragma unroll
    for (int j = 0; j < K; j++) { bn[j] = (float)sc->b[j]; bp[j] = (float)sc->bp[j]; }

    for (int g = tid; g < ngrp; g += TPB) {
        float4 o[7];
        float* of = reinterpret_cast<float*>(o);
#pragma unroll
        for (int r = 0; r < 4; r++) {
            uint4 v = Es[(g << 2) + r];
            const __half2* h = reinterpret_cast<const __half2*>(&v);
            float2 f0 = __half22float2(h[0]);
            float2 f1 = __half22float2(h[1]);
            float2 f2 = __half22float2(h[2]);
            float2 f3 = __half22float2(h[3]);
            float dot = f0.x * bp[0];
            dot = fmaf(f0.y, bp[1], dot);
            dot = fmaf(f1.x, bp[2], dot);
            dot = fmaf(f1.y, bp[3], dot);
            dot = fmaf(f2.x, bp[4], dot);
            dot = fmaf(f2.y, bp[5], dot);
            dot = fmaf(f3.x, bp[6], dot);
            float inv = frcp(dot);
            of[r * 7 + 0] = f0.x * bn[0] * inv;
            of[r * 7 + 1] = f0.y * bn[1] * inv;
            of[r * 7 + 2] = f1.x * bn[2] * inv;
            of[r * 7 + 3] = f1.y * bn[3] * inv;
            of[r * 7 + 4] = f2.x * bn[4] * inv;
            of[r * 7 + 5] = f2.y * bn[5] * inv;
            of[r * 7 + 6] = f3.x * bn[6] * inv;
        }
        float4* od = reinterpret_cast<float4*>(out + (size_t)(base + (g << 2)) * K);
#pragma unroll
        for (int i = 0; i < 7; i++) od[i] = o[i];   // 4 rows = 7 STG.128
    }
}

// ---------------------------------------------------------------------------
extern "C" void kernel_launch(void* const* d_in, const int* in_sizes, int n_in,
                              void* d_out, int out_size) {
    const float* P = (const float*)d_in[0];
    float* out = (float*)d_out;
    (void)in_sizes; (void)n_in; (void)out_size;

    static int configured = 0;
    if (!configured) {
        cudaFuncSetAttribute(k_main, cudaFuncAttributeMaxDynamicSharedMemorySize,
                             (int)DYN_SMEM);
        configured = 1;
    }
    k_init<<<1, 512>>>();                       // reset barrier/reduction state
    k_main<<<GRID, TPB, DYN_SMEM>>>(P, out);    // everything else, one launch
}